// round 13
// baseline (speedup 1.0000x reference)
#include <cuda_runtime.h>
#include <math.h>

#define NN       1024
#define NEVALC   131072
#define NPOLES   8
#define NGROUPS  256          // 4 nodes per group
#define GRID     128
#define BLOCK    512
#define ESHIFT   1010         // binary recentering ~= 700/ln2 (cancels in num/den)

typedef unsigned long long ull;

// ---------------- compile-time Chebyshev nodes --------------------------------------
constexpr double CPI = 3.141592653589793238462643383279502884;
constexpr double ccos_t(double z) {            // |z| <= pi/4
    double t = 1.0, s = 1.0, z2 = z * z;
    for (int k = 1; k <= 12; k++) { t *= -z2 / ((2.0 * k - 1.0) * (2.0 * k)); s += t; }
    return s;
}
constexpr double csin_t(double z) {            // |z| <= pi/4
    double t = z, s = z, z2 = z * z;
    for (int k = 1; k <= 12; k++) { t *= -z2 / ((2.0 * k) * (2.0 * k + 1.0)); s += t; }
    return s;
}
constexpr double cospi_c(double x) {           // x in [0,1]
    double r = x; bool neg = false;
    if (r > 0.5) { r = 1.0 - r; neg = true; }
    double v = (r <= 0.25) ? ccos_t(CPI * r) : csin_t(CPI * (0.5 - r));
    return neg ? -v : v;
}
struct alignas(16) NodeTab { float v[NN]; };
constexpr NodeTab mk_nodes() {
    NodeTab n{};
    for (int i = 0; i < NN; i++) n.v[i] = (float)cospi_c((double)i / 1023.0);
    return n;
}
__device__ constexpr NodeTab c_nodes = mk_nodes();

// ---------------- scratch / constant coefficient table ------------------------------
// 16 floats per group: [-cf, q3, q2, q1 | q0, pv3, pv2, pv1 | pv0, pw3, pw2, pw1 | pw0, 0,0,0]
__device__ float  g_coefF[NGROUPS * 16];
__constant__ float4 c_cf[NGROUPS * 4];       // same data, constant space -> LDCU/UR operands

// ---------------- helpers ----------------
__device__ __forceinline__ float frcp(float a) {
    float r; asm("rcp.approx.f32 %0,%1;" : "=f"(r) : "f"(a)); return r;
}
// strip exponent of a positive normal float into an int accumulator (no fp64/MUFU)
__device__ __forceinline__ void renorm(float& p, int& e) {
    int b = __float_as_int(p);
    e += (b >> 23) - 127;
    p = __int_as_float((b & 0x007fffff) | 0x3f800000);
}

// ---------------- P0: prep — weights + group coefficients ---------------------------
// grid 128 x block 512. Block b owns nodes 8b..8b+7 and groups 2b, 2b+1.
__global__ __launch_bounds__(512) void k_prep(const float* __restrict__ vals,
                                              const float* __restrict__ pr,
                                              const float* __restrict__ pim) {
    __shared__ float snodes[NN];
    __shared__ float sw[8];
    __shared__ float spf[8];
    __shared__ int   spe[8];
    int tid = threadIdx.x;
    int w   = tid >> 5;
    int ln  = tid & 31;

    ((float2*)snodes)[tid] = ((const float2*)c_nodes.v)[tid];
    __syncthreads();

    // weights via f32 product + integer exponent tracking (no logf/expf/fp64).
    // Reference's max-normalization is a COMMON factor and cancels in num/den;
    // ESHIFT is the binary equivalent of the validated LOGC=700 recentering.
    {
        int j = blockIdx.x * 8 + (w & 7);
        int h = w >> 3;
        float nj = snodes[j];
        float p = 1.0f; int e = 0;
        #pragma unroll 4
        for (int i = ln + 32 * h; i < NN; i += 64) {
            float d = (i != j) ? fabsf(nj - snodes[i]) : 1.0f;
            p *= d;
            renorm(p, e);
        }
        #pragma unroll
        for (int off = 16; off; off >>= 1) {
            p *= __shfl_xor_sync(0xffffffffu, p, off);
            e += __shfl_xor_sync(0xffffffffu, e, off);
            renorm(p, e);
        }
        if (ln == 0 && h == 1) { spf[w & 7] = p; spe[w & 7] = e; }
        __syncthreads();
        if (ln == 0 && h == 0) {
            float pf = p * spf[w]; int ef = e + spe[w];
            renorm(pf, ef);
            float pp = 1.0f; int ep = 0;
            #pragma unroll
            for (int q = 0; q < NPOLES; q++) {
                float dr = nj - pr[q];
                float inner = dr * dr + pim[q] * pim[q];   // f32, like reference
                pp *= inner;
                renorm(pp, ep);
            }
            float m  = pp * frcp(pf);
            float wv = ldexpf(m, ep - ef - ESHIFT);
            sw[w] = (j & 1) ? -wv : wv;        // sign = (-1)^j (nodes descending)
        }
    }
    __syncthreads();

    // group-rational coefficients (fp64, 4 lanes per group, 2 groups/block)
    //   Q(t)  = prod (t - d_i)                     (monic quartic)
    //   Pv(t) = sum v_i*w_i * prod_{j!=i}(t - d_j) (cubic)
    //   Pw(t) = sum     w_i * prod_{j!=i}(t - d_j) (cubic)
    if (tid < 8) {
        int g  = blockIdx.x * 2 + (tid >> 2);
        int i  = tid & 3;
        double n[4];
        #pragma unroll
        for (int k = 0; k < 4; k++) n[k] = (double)snodes[4 * g + k];
        float cf = (float)(0.25 * (n[0] + n[1] + n[2] + n[3]));
        double d[4];
        #pragma unroll
        for (int k = 0; k < 4; k++) d[k] = n[k] - (double)cf;
        double e1 = d[0] + d[1] + d[2] + d[3];
        double e2 = d[0]*d[1] + d[0]*d[2] + d[0]*d[3] + d[1]*d[2] + d[1]*d[3] + d[2]*d[3];
        double e3 = d[0]*d[1]*d[2] + d[0]*d[1]*d[3] + d[0]*d[2]*d[3] + d[1]*d[2]*d[3];
        double e4 = d[0]*d[1]*d[2]*d[3];
        double u  = (double)sw[(tid >> 2) * 4 + i];
        double uv = u * (double)vals[4 * g + i];
        double s1 = e1 - d[i];
        double s2 = e2 - d[i] * s1;
        double s3 = e3 - d[i] * s2;
        double red[8] = { uv, -uv * s1,  uv * s2, -uv * s3,
                          u,  -u  * s1,  u  * s2, -u  * s3 };
        #pragma unroll
        for (int k = 0; k < 8; k++) {
            red[k] += __shfl_down_sync(0xffu, red[k], 2, 4);
            red[k] += __shfl_down_sync(0xffu, red[k], 1, 4);
        }
        if (i == 0) {
            float* gc = g_coefF + (size_t)g * 16;
            gc[0]  = -cf;
            gc[1]  = (float)(-e1);   // q3
            gc[2]  = (float)( e2);   // q2
            gc[3]  = (float)(-e3);   // q1
            gc[4]  = (float)( e4);   // q0
            gc[5]  = (float)red[0];  // pv3
            gc[6]  = (float)red[1];
            gc[7]  = (float)red[2];
            gc[8]  = (float)red[3];
            gc[9]  = (float)red[4];  // pw3
            gc[10] = (float)red[5];
            gc[11] = (float)red[6];
            gc[12] = (float)red[7];
            gc[13] = 0.f; gc[14] = 0.f; gc[15] = 0.f;
        }
    }
}

// ---------------- P1: eval — scalar fp32, coefficients from __constant__ ------------
// block 512 = 4 partitions x 128 point-lanes, grid 128. Partition p accumulates
// groups 64p..64p+63 as 32 merged pairs (i, i+32): one rcp per 2 groups via
// V_A/Q_A + V_B/Q_B = (V_A Q_B + V_B Q_A)/(Q_A Q_B). Coefficients are warp-uniform
// __constant__ reads -> LDCU/uniform-register FFMA operands (2 distinct regular
// regs per FMA -> banking allows rt=1, vs rt=2 for the 3-reg form).
__global__ __launch_bounds__(512) void k_eval(const float* __restrict__ x,
                                              float* __restrict__ out) {
    __shared__ float sred[3][128][16];

    int tid  = threadIdx.x;
    int part = tid >> 7;                       // group partition 0..3
    int lane = tid & 127;                      // point-lane
    int quad0 = blockIdx.x * 256 + lane;       // coalesced float4 accesses
    int quad1 = quad0 + 128;
    float4 va = ((const float4*)x)[quad0];
    float4 vb = ((const float4*)x)[quad1];
    float xx[8] = { va.x, va.y, va.z, va.w, vb.x, vb.y, vb.z, vb.w };
    float nm[8] = {0,0,0,0,0,0,0,0};
    float dn[8] = {0,0,0,0,0,0,0,0};

    const float4* cA = c_cf + (part * 64) * 4;
    const float4* cB = cA + 32 * 4;

    #pragma unroll 2
    for (int i = 0; i < 32; i++) {
        float4 a0 = cA[0], a1 = cA[1], a2 = cA[2], a3 = cA[3];
        float4 b0 = cB[0], b1 = cB[1], b2 = cB[2], b3 = cB[3];
        cA += 4; cB += 4;

        #pragma unroll
        for (int p = 0; p < 8; p++) {
            float xv = xx[p];
            float tA = xv + a0.x;              // t = x - c_A
            float tB = xv + b0.x;              // t = x - c_B
            float qA = tA + a0.y;              // monic quartic Horner A
            qA = fmaf(qA, tA, a0.z);
            qA = fmaf(qA, tA, a0.w);
            qA = fmaf(qA, tA, a1.x);
            float qB = tB + b0.y;              // monic quartic Horner B
            qB = fmaf(qB, tB, b0.z);
            qB = fmaf(qB, tB, b0.w);
            qB = fmaf(qB, tB, b1.x);
            float vA = fmaf(a1.y, tA, a1.z);   // cubic num A
            vA = fmaf(vA, tA, a1.w);
            vA = fmaf(vA, tA, a2.x);
            float vB = fmaf(b1.y, tB, b1.z);   // cubic num B
            vB = fmaf(vB, tB, b1.w);
            vB = fmaf(vB, tB, b2.x);
            float wA = fmaf(a2.y, tA, a2.z);   // cubic den A
            wA = fmaf(wA, tA, a2.w);
            wA = fmaf(wA, tA, a3.x);
            float wB = fmaf(b2.y, tB, b2.z);   // cubic den B
            wB = fmaf(wB, tB, b2.w);
            wB = fmaf(wB, tB, b3.x);
            float qq = qA * qB;
            float r  = frcp(qq);               // 1 rcp per 2 groups
            float vc = vA * qB;
            vc = fmaf(vB, qA, vc);
            float wc = wA * qB;
            wc = fmaf(wB, qA, wc);
            nm[p] = fmaf(vc, r, nm[p]);
            dn[p] = fmaf(wc, r, dn[p]);
        }
    }

    // cross-partition reduction + divide + store
    if (part) {
        float* dst = sred[part - 1][lane];
        #pragma unroll
        for (int p = 0; p < 8; p++) { dst[p] = nm[p]; dst[8 + p] = dn[p]; }
    }
    __syncthreads();
    if (part == 0) {
        #pragma unroll
        for (int q = 0; q < 3; q++) {
            const float* s = sred[q][lane];
            #pragma unroll
            for (int p = 0; p < 8; p++) { nm[p] += s[p]; dn[p] += s[8 + p]; }
        }
        float4 o;
        o.x = nm[0] * frcp(dn[0]);
        o.y = nm[1] * frcp(dn[1]);
        o.z = nm[2] * frcp(dn[2]);
        o.w = nm[3] * frcp(dn[3]);
        ((float4*)out)[quad0] = o;
        o.x = nm[4] * frcp(dn[4]);
        o.y = nm[5] * frcp(dn[5]);
        o.z = nm[6] * frcp(dn[6]);
        o.w = nm[7] * frcp(dn[7]);
        ((float4*)out)[quad1] = o;
    }
}

// ---------------- launch ----------------
extern "C" void kernel_launch(void* const* d_in, const int* in_sizes, int n_in,
                              void* d_out, int out_size) {
    const float* x    = (const float*)d_in[0];
    const float* vals = (const float*)d_in[1];
    const float* pr   = (const float*)d_in[2];
    const float* pim  = (const float*)d_in[3];
    float* out = (float*)d_out;

    k_prep<<<GRID, BLOCK>>>(vals, pr, pim);

    // copy coefficients into constant space (async D2D memcpy: graph-capturable,
    // no allocation). Constant caches are invalidated at kernel-launch boundaries.
    void* csym = nullptr;
    void* gsym = nullptr;
    cudaGetSymbolAddress(&csym, c_cf);
    cudaGetSymbolAddress(&gsym, g_coefF);
    cudaMemcpyAsync(csym, gsym, NGROUPS * 16 * sizeof(float),
                    cudaMemcpyDeviceToDevice, 0);

    k_eval<<<GRID, BLOCK>>>(x, out);
}

// round 14
// speedup vs baseline: 1.1660x; 1.1660x over previous
#include <cuda_runtime.h>
#include <math.h>

#define NN       1024
#define NEVALC   131072
#define NPOLES   8
#define NOCT     120          // octets: nodes 32..991
#define NQRT     16           // quartets: nodes 0..31 and 992..1023
#define GRID     128
#define BLOCK    512
#define ESHIFT   1010         // binary recentering ~= 700/ln2 (cancels in num/den)

typedef unsigned long long ull;

// ---------------- compile-time Chebyshev nodes --------------------------------------
constexpr double CPI = 3.141592653589793238462643383279502884;
constexpr double ccos_t(double z) {
    double t = 1.0, s = 1.0, z2 = z * z;
    for (int k = 1; k <= 12; k++) { t *= -z2 / ((2.0 * k - 1.0) * (2.0 * k)); s += t; }
    return s;
}
constexpr double csin_t(double z) {
    double t = z, s = z, z2 = z * z;
    for (int k = 1; k <= 12; k++) { t *= -z2 / ((2.0 * k) * (2.0 * k + 1.0)); s += t; }
    return s;
}
constexpr double cospi_c(double x) {
    double r = x; bool neg = false;
    if (r > 0.5) { r = 1.0 - r; neg = true; }
    double v = (r <= 0.25) ? ccos_t(CPI * r) : csin_t(CPI * (0.5 - r));
    return neg ? -v : v;
}
struct alignas(16) NodeTab { float v[NN]; };
constexpr NodeTab mk_nodes() {
    NodeTab n{};
    for (int i = 0; i < NN; i++) n.v[i] = (float)cospi_c((double)i / 1023.0);
    return n;
}
__device__ constexpr NodeTab c_nodes = mk_nodes();

// ---------------- scratch ----------------
// octet o: 26 dup-packed ull at o*26; quartet q: 14 at 120*26 + q*14. Total 3344 ull.
__device__ ulonglong2 g_coef[(NOCT * 26 + NQRT * 14) / 2];
__device__ unsigned   g_bar;

// ---------------- packed f32x2 helpers ----------------
__device__ __forceinline__ ull pk2(float lo, float hi) {
    ull r; asm("mov.b64 %0,{%1,%2};" : "=l"(r) : "f"(lo), "f"(hi)); return r;
}
__device__ __forceinline__ void upk2(ull v, float& lo, float& hi) {
    asm("mov.b64 {%0,%1},%2;" : "=f"(lo), "=f"(hi) : "l"(v));
}
__device__ __forceinline__ ull f2fma(ull a, ull b, ull c) {
    ull d; asm("fma.rn.f32x2 %0,%1,%2,%3;" : "=l"(d) : "l"(a), "l"(b), "l"(c)); return d;
}
__device__ __forceinline__ ull f2add(ull a, ull b) {
    ull d; asm("add.rn.f32x2 %0,%1,%2;" : "=l"(d) : "l"(a), "l"(b)); return d;
}
__device__ __forceinline__ ull f2mul(ull a, ull b) {
    ull d; asm("mul.rn.f32x2 %0,%1,%2;" : "=l"(d) : "l"(a), "l"(b)); return d;
}
__device__ __forceinline__ ull f2rcp(ull q) {
    ull r;
    asm("{.reg .f32 lo, hi;\n\t"
        "mov.b64 {lo, hi}, %1;\n\t"
        "rcp.approx.f32 lo, lo;\n\t"
        "rcp.approx.f32 hi, hi;\n\t"
        "mov.b64 %0, {lo, hi};}"
        : "=l"(r) : "l"(q));
    return r;
}
__device__ __forceinline__ float frcp(float a) {
    float r; asm("rcp.approx.f32 %0,%1;" : "=f"(r) : "f"(a)); return r;
}
__device__ __forceinline__ unsigned ldacq(unsigned* p) {
    unsigned v; asm volatile("ld.acquire.gpu.u32 %0,[%1];" : "=r"(v) : "l"(p)); return v;
}
__device__ __forceinline__ void renorm(float& p, int& e) {
    int b = __float_as_int(p);
    e += (b >> 23) - 127;
    p = __int_as_float((b & 0x007fffff) | 0x3f800000);
}

// ---------------- fused kernel ----------------
__global__ __launch_bounds__(512) void k_all(const float* __restrict__ x,
                                             const float* __restrict__ vals,
                                             const float* __restrict__ pr,
                                             const float* __restrict__ pim,
                                             float* __restrict__ out) {
    __shared__ float snodes[NN];
    __shared__ float sw[12];
    __shared__ ulonglong2 sc[(NOCT * 26 + NQRT * 14) / 2];   // 26.75 KB, reused for reduction

    int tid = threadIdx.x;
    int w   = tid >> 5;
    int ln  = tid & 31;
    int b   = blockIdx.x;

    ((float2*)snodes)[tid] = ((const float2*)c_nodes.v)[tid];
    __syncthreads();

    // ---- weights (f32 product + integer exponent tracking; no logf/expf/fp64) ----
    // Block b owns: octet b (nodes 32+8b..39+8b) if b<120 -> warps 0..7;
    //               quartet b (nodes 4b.. or 992+4(b-8)..) if b<16 -> warps 8..11.
    {
        int node = -1;
        if (w < 8) { if (b < NOCT) node = 32 + 8 * b + w; }
        else if (w < 12) { if (b < NQRT) node = ((b < 8) ? 4 * b : 992 + 4 * (b - 8)) + (w - 8); }
        if (node >= 0) {
            float nj = snodes[node];
            float p = 1.0f; int e = 0;
            #pragma unroll 4
            for (int i = ln; i < NN; i += 32) {
                float d = (i != node) ? fabsf(nj - snodes[i]) : 1.0f;
                p *= d;
                renorm(p, e);
            }
            #pragma unroll
            for (int off = 16; off; off >>= 1) {
                p *= __shfl_xor_sync(0xffffffffu, p, off);
                e += __shfl_xor_sync(0xffffffffu, e, off);
                renorm(p, e);
            }
            if (ln == 0) {
                float pp = 1.0f; int ep = 0;
                #pragma unroll
                for (int q = 0; q < NPOLES; q++) {
                    float dr = nj - pr[q];
                    float inner = dr * dr + pim[q] * pim[q];
                    pp *= inner;
                    renorm(pp, ep);
                }
                float m  = pp * frcp(p);
                float wv = ldexpf(m, ep - e - ESHIFT);
                sw[w] = (node & 1) ? -wv : wv;   // sign = (-1)^j
            }
        }
    }
    __syncthreads();

    // ---- octet coefficients (warp 12, fp64, lanes 0..7 = roots) ----
    // Q(t)=prod(t-d_i) monic octic; Pv=sum uv_i*prod_{j!=i}; Pw=sum u_i*prod_{j!=i}.
    if (w == 12 && b < NOCT) {
        bool act = ln < 8;
        int nodei = 32 + 8 * b + (ln & 7);
        double nd = act ? (double)snodes[nodei] : 0.0;
        double s = nd;
        s += __shfl_xor_sync(0xffffffffu, s, 1);
        s += __shfl_xor_sync(0xffffffffu, s, 2);
        s += __shfl_xor_sync(0xffffffffu, s, 4);
        float cf = (float)(0.125 * s);
        double di = nd - (double)cf;
        double dd[8];
        #pragma unroll
        for (int k = 0; k < 8; k++) dd[k] = __shfl_sync(0xffffffffu, di, k);
        double C[9];
        C[0] = 1.0;
        #pragma unroll
        for (int k = 1; k < 9; k++) C[k] = 0.0;
        #pragma unroll
        for (int r = 0; r < 8; r++) {
            #pragma unroll
            for (int k = 8; k >= 1; k--) C[k] = C[k - 1] - dd[r] * C[k];
            C[0] = -dd[r] * C[0];
        }
        double B[8];
        B[7] = 1.0;
        #pragma unroll
        for (int k = 6; k >= 0; k--) B[k] = C[k + 1] + di * B[k + 1];
        double u  = act ? (double)sw[ln & 7] : 0.0;
        double uv = u * (act ? (double)vals[nodei] : 0.0);
        double pv[8], pw[8];
        #pragma unroll
        for (int k = 0; k < 8; k++) {
            double a = uv * B[k], c2 = u * B[k];
            #pragma unroll
            for (int off = 4; off; off >>= 1) {
                a  += __shfl_xor_sync(0xffffffffu, a, off);
                c2 += __shfl_xor_sync(0xffffffffu, c2, off);
            }
            pv[k] = a; pw[k] = c2;
        }
        if (ln == 0) {
            ull* cc = (ull*)g_coef + (size_t)b * 26;
            float f;
            f = -cf;           cc[0]  = pk2(f, f);
            #pragma unroll
            for (int k = 0; k < 8; k++) { f = (float)C[7 - k];  cc[1 + k]  = pk2(f, f); }
            #pragma unroll
            for (int k = 0; k < 8; k++) { f = (float)pv[7 - k]; cc[9 + k]  = pk2(f, f); }
            #pragma unroll
            for (int k = 0; k < 8; k++) { f = (float)pw[7 - k]; cc[17 + k] = pk2(f, f); }
            cc[25] = 0ull;
            __threadfence();
        }
    }

    // ---- quartet coefficients (warp 13, fp64, lanes 0..3 = roots) ----
    if (w == 13 && b < NQRT) {
        bool act = ln < 4;
        int nb = (b < 8) ? 4 * b : 992 + 4 * (b - 8);
        int nodei = nb + (ln & 3);
        double nd = act ? (double)snodes[nodei] : 0.0;
        double s = nd;
        s += __shfl_xor_sync(0xffffffffu, s, 1);
        s += __shfl_xor_sync(0xffffffffu, s, 2);
        float cf = (float)(0.25 * s);
        double di = nd - (double)cf;
        double dd[4];
        #pragma unroll
        for (int k = 0; k < 4; k++) dd[k] = __shfl_sync(0xffffffffu, di, k);
        double C[5];
        C[0] = 1.0;
        #pragma unroll
        for (int k = 1; k < 5; k++) C[k] = 0.0;
        #pragma unroll
        for (int r = 0; r < 4; r++) {
            #pragma unroll
            for (int k = 4; k >= 1; k--) C[k] = C[k - 1] - dd[r] * C[k];
            C[0] = -dd[r] * C[0];
        }
        double B[4];
        B[3] = 1.0;
        #pragma unroll
        for (int k = 2; k >= 0; k--) B[k] = C[k + 1] + di * B[k + 1];
        double u  = act ? (double)sw[8 + (ln & 3)] : 0.0;
        double uv = u * (act ? (double)vals[nodei] : 0.0);
        double pv[4], pw[4];
        #pragma unroll
        for (int k = 0; k < 4; k++) {
            double a = uv * B[k], c2 = u * B[k];
            #pragma unroll
            for (int off = 2; off; off >>= 1) {
                a  += __shfl_xor_sync(0xffffffffu, a, off);
                c2 += __shfl_xor_sync(0xffffffffu, c2, off);
            }
            pv[k] = a; pw[k] = c2;
        }
        if (ln == 0) {
            ull* cc = (ull*)g_coef + (size_t)NOCT * 26 + (size_t)b * 14;
            float f;
            f = -cf;           cc[0]  = pk2(f, f);
            #pragma unroll
            for (int k = 0; k < 4; k++) { f = (float)C[3 - k];  cc[1 + k] = pk2(f, f); }
            #pragma unroll
            for (int k = 0; k < 4; k++) { f = (float)pv[3 - k]; cc[5 + k] = pk2(f, f); }
            #pragma unroll
            for (int k = 0; k < 4; k++) { f = (float)pw[3 - k]; cc[9 + k] = pk2(f, f); }
            cc[13] = 0ull;
            __threadfence();
        }
    }

    // ---- x loads (hidden behind the barrier) ----
    int part = tid >> 8;                       // 0..1
    int lane = tid & 255;
    int quad = b * 256 + lane;
    float4 xv = ((const float4*)x)[quad];
    ull xp0 = pk2(xv.x, xv.y), xp1 = pk2(xv.z, xv.w);

    // ---- grid barrier (monotonic tickets; 1 block/SM) ----
    __syncthreads();
    if (tid == 0) {
        unsigned ticket = atomicAdd(&g_bar, 1u);
        unsigned target = (ticket / GRID + 1u) * GRID;
        while (ldacq(&g_bar) < target) { }
    }
    __syncthreads();

    // ---- load all coefficients into smem ----
    {
        const uint4* src = (const uint4*)g_coef;
        uint4* dst = (uint4*)sc;
        #pragma unroll
        for (int i = tid; i < (NOCT * 26 + NQRT * 14) / 2; i += BLOCK) dst[i] = src[i];
    }
    __syncthreads();

    // ---- eval: 4 pts/thread (2 packed pairs), split-2 over groups.
    //      rcp merged across group pairs: V_A/Q_A + V_B/Q_B = (V_A Q_B + V_B Q_A)/(Q_A Q_B).
    //      Octet pairs (o, o+30); quartet pairs across opposite ends (q, q+8).
    ull nm0 = 0, dn0 = 0, nm1 = 0, dn1 = 0;

    // octets: partition p handles octets 60p..60p+59 as pairs (60p+i, 60p+i+30)
    const ulonglong2* oA = sc + (size_t)(60 * part) * 13;
    const ulonglong2* oB = oA + (size_t)30 * 13;

    #pragma unroll 3
    for (int i = 0; i < 30; i++) {
        ulonglong2 a0 = oA[0], a1 = oA[1], a2 = oA[2],  a3 = oA[3],  a4 = oA[4],
                   a5 = oA[5], a6 = oA[6], a7 = oA[7],  a8 = oA[8],  a9 = oA[9],
                   a10 = oA[10], a11 = oA[11], a12 = oA[12];
        ulonglong2 b0 = oB[0], b1 = oB[1], b2 = oB[2],  b3 = oB[3],  b4 = oB[4],
                   b5 = oB[5], b6 = oB[6], b7 = oB[7],  b8 = oB[8],  b9 = oB[9],
                   b10 = oB[10], b11 = oB[11], b12 = oB[12];
        oA += 13; oB += 13;

        #define GRP2OCT(XP, NM, DN)                                           \
        {                                                                     \
            ull tA = f2add(XP, a0.x);                                         \
            ull tB = f2add(XP, b0.x);                                         \
            ull qA = f2add(tA, a0.y);          /* monic octic Horner A */     \
            qA = f2fma(qA, tA, a1.x);  qA = f2fma(qA, tA, a1.y);              \
            qA = f2fma(qA, tA, a2.x);  qA = f2fma(qA, tA, a2.y);              \
            qA = f2fma(qA, tA, a3.x);  qA = f2fma(qA, tA, a3.y);              \
            qA = f2fma(qA, tA, a4.x);                                         \
            ull qB = f2add(tB, b0.y);                                         \
            qB = f2fma(qB, tB, b1.x);  qB = f2fma(qB, tB, b1.y);              \
            qB = f2fma(qB, tB, b2.x);  qB = f2fma(qB, tB, b2.y);              \
            qB = f2fma(qB, tB, b3.x);  qB = f2fma(qB, tB, b3.y);              \
            qB = f2fma(qB, tB, b4.x);                                         \
            ull vA = f2fma(a4.y, tA, a5.x);    /* septic num A */             \
            vA = f2fma(vA, tA, a5.y);  vA = f2fma(vA, tA, a6.x);              \
            vA = f2fma(vA, tA, a6.y);  vA = f2fma(vA, tA, a7.x);              \
            vA = f2fma(vA, tA, a7.y);  vA = f2fma(vA, tA, a8.x);              \
            ull vB = f2fma(b4.y, tB, b5.x);                                   \
            vB = f2fma(vB, tB, b5.y);  vB = f2fma(vB, tB, b6.x);              \
            vB = f2fma(vB, tB, b6.y);  vB = f2fma(vB, tB, b7.x);              \
            vB = f2fma(vB, tB, b7.y);  vB = f2fma(vB, tB, b8.x);              \
            ull wA = f2fma(a8.y, tA, a9.x);    /* septic den A */             \
            wA = f2fma(wA, tA, a9.y);  wA = f2fma(wA, tA, a10.x);             \
            wA = f2fma(wA, tA, a10.y); wA = f2fma(wA, tA, a11.x);             \
            wA = f2fma(wA, tA, a11.y); wA = f2fma(wA, tA, a12.x);             \
            ull wB = f2fma(b8.y, tB, b9.x);                                   \
            wB = f2fma(wB, tB, b9.y);  wB = f2fma(wB, tB, b10.x);             \
            wB = f2fma(wB, tB, b10.y); wB = f2fma(wB, tB, b11.x);             \
            wB = f2fma(wB, tB, b11.y); wB = f2fma(wB, tB, b12.x);             \
            ull qq = f2mul(qA, qB);                                           \
            ull r  = f2rcp(qq);                                               \
            ull vc = f2mul(vA, qB);  vc = f2fma(vB, qA, vc);                  \
            ull wc = f2mul(wA, qB);  wc = f2fma(wB, qA, wc);                  \
            NM = f2fma(vc, r, NM);                                            \
            DN = f2fma(wc, r, DN);                                            \
        }
        GRP2OCT(xp0, nm0, dn0)
        GRP2OCT(xp1, nm1, dn1)
        #undef GRP2OCT
    }

    // quartets: partition p pairs (4p+k, 4p+k+8), k=0..3 (opposite ends)
    {
        const ulonglong2* qb = sc + (size_t)NOCT * 13;
        #pragma unroll
        for (int k = 0; k < 4; k++) {
            const ulonglong2* A = qb + (size_t)(4 * part + k) * 7;
            const ulonglong2* Bq = qb + (size_t)(4 * part + k + 8) * 7;
            ulonglong2 a0 = A[0], a1 = A[1], a2 = A[2], a3 = A[3],
                       a4 = A[4], a5 = A[5], a6 = A[6];
            ulonglong2 b0 = Bq[0], b1 = Bq[1], b2 = Bq[2], b3 = Bq[3],
                       b4 = Bq[4], b5 = Bq[5], b6 = Bq[6];

            #define GRP2QRT(XP, NM, DN)                                       \
            {                                                                 \
                ull tA = f2add(XP, a0.x);                                     \
                ull tB = f2add(XP, b0.x);                                     \
                ull qA = f2add(tA, a0.y);                                     \
                qA = f2fma(qA, tA, a1.x);  qA = f2fma(qA, tA, a1.y);          \
                qA = f2fma(qA, tA, a2.x);                                     \
                ull qB = f2add(tB, b0.y);                                     \
                qB = f2fma(qB, tB, b1.x);  qB = f2fma(qB, tB, b1.y);          \
                qB = f2fma(qB, tB, b2.x);                                     \
                ull vA = f2fma(a2.y, tA, a3.x);                               \
                vA = f2fma(vA, tA, a3.y);  vA = f2fma(vA, tA, a4.x);          \
                ull vB = f2fma(b2.y, tB, b3.x);                               \
                vB = f2fma(vB, tB, b3.y);  vB = f2fma(vB, tB, b4.x);          \
                ull wA = f2fma(a4.y, tA, a5.x);                               \
                wA = f2fma(wA, tA, a5.y);  wA = f2fma(wA, tA, a6.x);          \
                ull wB = f2fma(b4.y, tB, b5.x);                               \
                wB = f2fma(wB, tB, b5.y);  wB = f2fma(wB, tB, b6.x);          \
                ull qq = f2mul(qA, qB);                                       \
                ull r  = f2rcp(qq);                                           \
                ull vc = f2mul(vA, qB);  vc = f2fma(vB, qA, vc);              \
                ull wc = f2mul(wA, qB);  wc = f2fma(wB, qA, wc);              \
                NM = f2fma(vc, r, NM);                                        \
                DN = f2fma(wc, r, DN);                                        \
            }
            GRP2QRT(xp0, nm0, dn0)
            GRP2QRT(xp1, nm1, dn1)
            #undef GRP2QRT
        }
    }

    // ---- cross-partition reduction (reuse sc) + divide + store ----
    __syncthreads();
    ull (*sred)[4] = (ull(*)[4])sc;            // 256 x 4 x 8B = 8 KB
    if (part) {
        sred[lane][0] = nm0; sred[lane][1] = dn0;
        sred[lane][2] = nm1; sred[lane][3] = dn1;
    }
    __syncthreads();
    if (part == 0) {
        nm0 = f2add(nm0, sred[lane][0]);
        dn0 = f2add(dn0, sred[lane][1]);
        nm1 = f2add(nm1, sred[lane][2]);
        dn1 = f2add(dn1, sred[lane][3]);
        float n0, n1, d0, d1;
        float4 o;
        upk2(nm0, n0, n1); upk2(dn0, d0, d1);
        o.x = n0 * frcp(d0); o.y = n1 * frcp(d1);
        upk2(nm1, n0, n1); upk2(dn1, d0, d1);
        o.z = n0 * frcp(d0); o.w = n1 * frcp(d1);
        ((float4*)out)[quad] = o;
    }
}

// ---------------- launch ----------------
extern "C" void kernel_launch(void* const* d_in, const int* in_sizes, int n_in,
                              void* d_out, int out_size) {
    const float* x    = (const float*)d_in[0];
    const float* vals = (const float*)d_in[1];
    const float* pr   = (const float*)d_in[2];
    const float* pim  = (const float*)d_in[3];
    float* out = (float*)d_out;

    k_all<<<GRID, BLOCK>>>(x, vals, pr, pim, out);
}

// round 15
// speedup vs baseline: 1.2357x; 1.0598x over previous
#include <cuda_runtime.h>
#include <math.h>

#define NN       1024
#define NEVALC   131072
#define NPOLES   8
#define NOCT     120          // octets: nodes 32..991
#define NQRT     16           // quartets: nodes 0..31 and 992..1023
#define GRID     128
#define BLOCK    512
#define ESHIFT   1010         // binary recentering ~= 700/ln2 (cancels in num/den)
#define NCU2     ((NOCT * 26 + NQRT * 14) / 2)   // ulonglong2 count = 1672 (26.75 KB)

typedef unsigned long long ull;

// ---------------- compile-time Chebyshev nodes --------------------------------------
constexpr double CPI = 3.141592653589793238462643383279502884;
constexpr double ccos_t(double z) {
    double t = 1.0, s = 1.0, z2 = z * z;
    for (int k = 1; k <= 12; k++) { t *= -z2 / ((2.0 * k - 1.0) * (2.0 * k)); s += t; }
    return s;
}
constexpr double csin_t(double z) {
    double t = z, s = z, z2 = z * z;
    for (int k = 1; k <= 12; k++) { t *= -z2 / ((2.0 * k) * (2.0 * k + 1.0)); s += t; }
    return s;
}
constexpr double cospi_c(double x) {
    double r = x; bool neg = false;
    if (r > 0.5) { r = 1.0 - r; neg = true; }
    double v = (r <= 0.25) ? ccos_t(CPI * r) : csin_t(CPI * (0.5 - r));
    return neg ? -v : v;
}
struct alignas(16) NodeTab { float v[NN]; };
constexpr NodeTab mk_nodes() {
    NodeTab n{};
    for (int i = 0; i < NN; i++) n.v[i] = (float)cospi_c((double)i / 1023.0);
    return n;
}
__device__ constexpr NodeTab c_nodes = mk_nodes();

// ---------------- scratch ----------------
// octet o: 26 dup-packed ull at o*26: [cM, q7..q0, pv7..pv0, pw7..pw0, pad]
// quartet q: 14 ull at 120*26 + q*14: [cM, q3..q0, pv3..pv0, pw3..pw0, pad]
__device__ ulonglong2 g_coef[NCU2];
__device__ unsigned   g_bar;

// ---------------- packed f32x2 helpers ----------------
__device__ __forceinline__ ull pk2(float lo, float hi) {
    ull r; asm("mov.b64 %0,{%1,%2};" : "=l"(r) : "f"(lo), "f"(hi)); return r;
}
__device__ __forceinline__ void upk2(ull v, float& lo, float& hi) {
    asm("mov.b64 {%0,%1},%2;" : "=f"(lo), "=f"(hi) : "l"(v));
}
__device__ __forceinline__ ull f2fma(ull a, ull b, ull c) {
    ull d; asm("fma.rn.f32x2 %0,%1,%2,%3;" : "=l"(d) : "l"(a), "l"(b), "l"(c)); return d;
}
__device__ __forceinline__ ull f2add(ull a, ull b) {
    ull d; asm("add.rn.f32x2 %0,%1,%2;" : "=l"(d) : "l"(a), "l"(b)); return d;
}
__device__ __forceinline__ ull f2rcp(ull q) {
    ull r;
    asm("{.reg .f32 lo, hi;\n\t"
        "mov.b64 {lo, hi}, %1;\n\t"
        "rcp.approx.f32 lo, lo;\n\t"
        "rcp.approx.f32 hi, hi;\n\t"
        "mov.b64 %0, {lo, hi};}"
        : "=l"(r) : "l"(q));
    return r;
}
__device__ __forceinline__ float frcp(float a) {
    float r; asm("rcp.approx.f32 %0,%1;" : "=f"(r) : "f"(a)); return r;
}
__device__ __forceinline__ unsigned ldacq(unsigned* p) {
    unsigned v; asm volatile("ld.acquire.gpu.u32 %0,[%1];" : "=r"(v) : "l"(p)); return v;
}
__device__ __forceinline__ void renorm(float& p, int& e) {
    int b = __float_as_int(p);
    e += (b >> 23) - 127;
    p = __int_as_float((b & 0x007fffff) | 0x3f800000);
}

// ---------------- fused kernel ----------------
__global__ __launch_bounds__(512) void k_all(const float* __restrict__ x,
                                             const float* __restrict__ vals,
                                             const float* __restrict__ pr,
                                             const float* __restrict__ pim,
                                             float* __restrict__ out) {
    __shared__ float snodes[NN];
    __shared__ float sw[12];
    __shared__ ulonglong2 sc[NCU2];            // coeffs; later reused for reduction

    int tid = threadIdx.x;
    int w   = tid >> 5;
    int ln  = tid & 31;
    int b   = blockIdx.x;

    ((float2*)snodes)[tid] = ((const float2*)c_nodes.v)[tid];
    __syncthreads();

    // ---- weights (f32 product + integer exponent tracking; no logf/expf/fp64) ----
    // Block b owns: octet b (nodes 32+8b..) if b<120 -> warps 0..7;
    //               quartet b (nodes 4b or 992+4(b-8)) if b<16 -> warps 8..11.
    {
        int node = -1;
        if (w < 8) { if (b < NOCT) node = 32 + 8 * b + w; }
        else if (w < 12) { if (b < NQRT) node = ((b < 8) ? 4 * b : 992 + 4 * (b - 8)) + (w - 8); }
        if (node >= 0) {
            float nj = snodes[node];
            float p = 1.0f; int e = 0;
            #pragma unroll 4
            for (int i = ln; i < NN; i += 32) {
                float d = (i != node) ? fabsf(nj - snodes[i]) : 1.0f;
                p *= d;
                renorm(p, e);
            }
            #pragma unroll
            for (int off = 16; off; off >>= 1) {
                p *= __shfl_xor_sync(0xffffffffu, p, off);
                e += __shfl_xor_sync(0xffffffffu, e, off);
                renorm(p, e);
            }
            if (ln == 0) {
                float pp = 1.0f; int ep = 0;
                #pragma unroll
                for (int q = 0; q < NPOLES; q++) {
                    float dr = nj - pr[q];
                    float inner = dr * dr + pim[q] * pim[q];
                    pp *= inner;
                    renorm(pp, ep);
                }
                float m  = pp * frcp(p);
                float wv = ldexpf(m, ep - e - ESHIFT);
                sw[w] = (node & 1) ? -wv : wv;   // sign = (-1)^j
            }
        }
    }
    __syncthreads();

    // ---- octet coefficients (warp 12, fp64, lanes 0..7 = roots) ----
    if (w == 12 && b < NOCT) {
        bool act = ln < 8;
        int nodei = 32 + 8 * b + (ln & 7);
        double nd = act ? (double)snodes[nodei] : 0.0;
        double s = nd;
        s += __shfl_xor_sync(0xffffffffu, s, 1);
        s += __shfl_xor_sync(0xffffffffu, s, 2);
        s += __shfl_xor_sync(0xffffffffu, s, 4);
        float cf = (float)(0.125 * s);
        double di = nd - (double)cf;
        double dd[8];
        #pragma unroll
        for (int k = 0; k < 8; k++) dd[k] = __shfl_sync(0xffffffffu, di, k);
        double C[9];
        C[0] = 1.0;
        #pragma unroll
        for (int k = 1; k < 9; k++) C[k] = 0.0;
        #pragma unroll
        for (int r = 0; r < 8; r++) {
            #pragma unroll
            for (int k = 8; k >= 1; k--) C[k] = C[k - 1] - dd[r] * C[k];
            C[0] = -dd[r] * C[0];
        }
        double B[8];
        B[7] = 1.0;
        #pragma unroll
        for (int k = 6; k >= 0; k--) B[k] = C[k + 1] + di * B[k + 1];
        double u  = act ? (double)sw[ln & 7] : 0.0;
        double uv = u * (act ? (double)vals[nodei] : 0.0);
        double pv[8], pw[8];
        #pragma unroll
        for (int k = 0; k < 8; k++) {
            double a = uv * B[k], c2 = u * B[k];
            #pragma unroll
            for (int off = 4; off; off >>= 1) {
                a  += __shfl_xor_sync(0xffffffffu, a, off);
                c2 += __shfl_xor_sync(0xffffffffu, c2, off);
            }
            pv[k] = a; pw[k] = c2;
        }
        if (ln == 0) {
            ull* cc = (ull*)g_coef + (size_t)b * 26;
            float f;
            f = -cf;           cc[0]  = pk2(f, f);
            #pragma unroll
            for (int k = 0; k < 8; k++) { f = (float)C[7 - k];  cc[1 + k]  = pk2(f, f); }
            #pragma unroll
            for (int k = 0; k < 8; k++) { f = (float)pv[7 - k]; cc[9 + k]  = pk2(f, f); }
            #pragma unroll
            for (int k = 0; k < 8; k++) { f = (float)pw[7 - k]; cc[17 + k] = pk2(f, f); }
            cc[25] = 0ull;
            __threadfence();
        }
    }

    // ---- quartet coefficients (warp 13, fp64, lanes 0..3 = roots) ----
    if (w == 13 && b < NQRT) {
        bool act = ln < 4;
        int nb = (b < 8) ? 4 * b : 992 + 4 * (b - 8);
        int nodei = nb + (ln & 3);
        double nd = act ? (double)snodes[nodei] : 0.0;
        double s = nd;
        s += __shfl_xor_sync(0xffffffffu, s, 1);
        s += __shfl_xor_sync(0xffffffffu, s, 2);
        float cf = (float)(0.25 * s);
        double di = nd - (double)cf;
        double dd[4];
        #pragma unroll
        for (int k = 0; k < 4; k++) dd[k] = __shfl_sync(0xffffffffu, di, k);
        double C[5];
        C[0] = 1.0;
        #pragma unroll
        for (int k = 1; k < 5; k++) C[k] = 0.0;
        #pragma unroll
        for (int r = 0; r < 4; r++) {
            #pragma unroll
            for (int k = 4; k >= 1; k--) C[k] = C[k - 1] - dd[r] * C[k];
            C[0] = -dd[r] * C[0];
        }
        double B[4];
        B[3] = 1.0;
        #pragma unroll
        for (int k = 2; k >= 0; k--) B[k] = C[k + 1] + di * B[k + 1];
        double u  = act ? (double)sw[8 + (ln & 3)] : 0.0;
        double uv = u * (act ? (double)vals[nodei] : 0.0);
        double pv[4], pw[4];
        #pragma unroll
        for (int k = 0; k < 4; k++) {
            double a = uv * B[k], c2 = u * B[k];
            #pragma unroll
            for (int off = 2; off; off >>= 1) {
                a  += __shfl_xor_sync(0xffffffffu, a, off);
                c2 += __shfl_xor_sync(0xffffffffu, c2, off);
            }
            pv[k] = a; pw[k] = c2;
        }
        if (ln == 0) {
            ull* cc = (ull*)g_coef + (size_t)NOCT * 26 + (size_t)b * 14;
            float f;
            f = -cf;           cc[0]  = pk2(f, f);
            #pragma unroll
            for (int k = 0; k < 4; k++) { f = (float)C[3 - k];  cc[1 + k] = pk2(f, f); }
            #pragma unroll
            for (int k = 0; k < 4; k++) { f = (float)pv[3 - k]; cc[5 + k] = pk2(f, f); }
            #pragma unroll
            for (int k = 0; k < 4; k++) { f = (float)pw[3 - k]; cc[9 + k] = pk2(f, f); }
            cc[13] = 0ull;
            __threadfence();
        }
    }

    // ---- x loads (hidden behind the barrier) ----
    int part  = tid >> 7;                      // group partition 0..3
    int lane  = tid & 127;                     // point-lane
    int quad0 = b * 256 + lane;
    int quad1 = quad0 + 128;
    float4 va = ((const float4*)x)[quad0];
    float4 vb = ((const float4*)x)[quad1];
    ull xp0 = pk2(va.x, va.y), xp1 = pk2(va.z, va.w);
    ull xp2 = pk2(vb.x, vb.y), xp3 = pk2(vb.z, vb.w);

    // ---- grid barrier (monotonic tickets; 1 block/SM) ----
    __syncthreads();
    if (tid == 0) {
        unsigned ticket = atomicAdd(&g_bar, 1u);
        unsigned target = (ticket / GRID + 1u) * GRID;
        while (ldacq(&g_bar) < target) { }
    }
    __syncthreads();

    // ---- load all coefficients into smem ----
    {
        const uint4* src = (const uint4*)g_coef;
        uint4* dst = (uint4*)sc;
        #pragma unroll
        for (int i = tid; i < NCU2; i += BLOCK) dst[i] = src[i];
    }
    __syncthreads();

    // ---- eval: 8 pts/thread (4 packed pairs), split-4 over groups, UNMERGED rcp
    //      (1 packed rcp per group per point-pair; its error multiplies num and den
    //      identically and cancels). Partition p: octets 30p..30p+29 and quartets
    //      {2p, 2p+1, 2p+8, 2p+9}. Single-group body keeps 13 ulonglong2 live.
    ull nm0 = 0, dn0 = 0, nm1 = 0, dn1 = 0, nm2 = 0, dn2 = 0, nm3 = 0, dn3 = 0;

    const ulonglong2* cp = sc + (size_t)(30 * part) * 13;
    #pragma unroll 2
    for (int i = 0; i < 30; i++) {
        ulonglong2 a0 = cp[0], a1 = cp[1], a2 = cp[2],  a3 = cp[3],  a4 = cp[4],
                   a5 = cp[5], a6 = cp[6], a7 = cp[7],  a8 = cp[8],  a9 = cp[9],
                   a10 = cp[10], a11 = cp[11], a12 = cp[12];
        cp += 13;

        #define GRPOCT(XP, NM, DN)                                            \
        {                                                                     \
            ull t = f2add(XP, a0.x);           /* t = x - c */                \
            ull q = f2add(t, a0.y);            /* monic octic Horner */       \
            q = f2fma(q, t, a1.x);   q = f2fma(q, t, a1.y);                   \
            q = f2fma(q, t, a2.x);   q = f2fma(q, t, a2.y);                   \
            q = f2fma(q, t, a3.x);   q = f2fma(q, t, a3.y);                   \
            q = f2fma(q, t, a4.x);                                            \
            ull v = f2fma(a4.y, t, a5.x);      /* septic num */               \
            v = f2fma(v, t, a5.y);   v = f2fma(v, t, a6.x);                   \
            v = f2fma(v, t, a6.y);   v = f2fma(v, t, a7.x);                   \
            v = f2fma(v, t, a7.y);   v = f2fma(v, t, a8.x);                   \
            ull wv = f2fma(a8.y, t, a9.x);     /* septic den */               \
            wv = f2fma(wv, t, a9.y);  wv = f2fma(wv, t, a10.x);               \
            wv = f2fma(wv, t, a10.y); wv = f2fma(wv, t, a11.x);               \
            wv = f2fma(wv, t, a11.y); wv = f2fma(wv, t, a12.x);               \
            ull r = f2rcp(q);                  /* 1 packed rcp / 8 nodes */   \
            NM = f2fma(v, r, NM);                                             \
            DN = f2fma(wv, r, DN);                                            \
        }
        GRPOCT(xp0, nm0, dn0)
        GRPOCT(xp1, nm1, dn1)
        GRPOCT(xp2, nm2, dn2)
        GRPOCT(xp3, nm3, dn3)
        #undef GRPOCT
    }

    // quartets {2p, 2p+1, 2p+8, 2p+9}
    {
        const ulonglong2* qb = sc + (size_t)NOCT * 13;
        #pragma unroll
        for (int k = 0; k < 4; k++) {
            int qi = (k < 2) ? (2 * part + k) : (2 * part + 8 + (k - 2));
            const ulonglong2* A = qb + (size_t)qi * 7;
            ulonglong2 a0 = A[0], a1 = A[1], a2 = A[2], a3 = A[3],
                       a4 = A[4], a5 = A[5], a6 = A[6];

            #define GRPQRT(XP, NM, DN)                                        \
            {                                                                 \
                ull t = f2add(XP, a0.x);                                      \
                ull q = f2add(t, a0.y);        /* monic quartic Horner */     \
                q = f2fma(q, t, a1.x);  q = f2fma(q, t, a1.y);                \
                q = f2fma(q, t, a2.x);                                        \
                ull v = f2fma(a2.y, t, a3.x);  /* cubic num */                \
                v = f2fma(v, t, a3.y);  v = f2fma(v, t, a4.x);                \
                ull wv = f2fma(a4.y, t, a5.x); /* cubic den */                \
                wv = f2fma(wv, t, a5.y); wv = f2fma(wv, t, a6.x);             \
                ull r = f2rcp(q);                                             \
                NM = f2fma(v, r, NM);                                         \
                DN = f2fma(wv, r, DN);                                        \
            }
            GRPQRT(xp0, nm0, dn0)
            GRPQRT(xp1, nm1, dn1)
            GRPQRT(xp2, nm2, dn2)
            GRPQRT(xp3, nm3, dn3)
            #undef GRPQRT
        }
    }

    // ---- cross-partition reduction (reuse sc) + divide + store ----
    __syncthreads();
    ull (*sred)[128][8] = (ull(*)[128][8])sc;   // 3 x 128 x 8 x 8B = 24 KB <= 26.75 KB
    if (part) {
        ull* dst = sred[part - 1][lane];
        dst[0] = nm0; dst[1] = dn0; dst[2] = nm1; dst[3] = dn1;
        dst[4] = nm2; dst[5] = dn2; dst[6] = nm3; dst[7] = dn3;
    }
    __syncthreads();
    if (part == 0) {
        #pragma unroll
        for (int p = 0; p < 3; p++) {
            const ull* s = sred[p][lane];
            nm0 = f2add(nm0, s[0]); dn0 = f2add(dn0, s[1]);
            nm1 = f2add(nm1, s[2]); dn1 = f2add(dn1, s[3]);
            nm2 = f2add(nm2, s[4]); dn2 = f2add(dn2, s[5]);
            nm3 = f2add(nm3, s[6]); dn3 = f2add(dn3, s[7]);
        }
        float n0, n1, d0, d1;
        float4 o;
        upk2(nm0, n0, n1); upk2(dn0, d0, d1);
        o.x = n0 * frcp(d0); o.y = n1 * frcp(d1);
        upk2(nm1, n0, n1); upk2(dn1, d0, d1);
        o.z = n0 * frcp(d0); o.w = n1 * frcp(d1);
        ((float4*)out)[quad0] = o;
        upk2(nm2, n0, n1); upk2(dn2, d0, d1);
        o.x = n0 * frcp(d0); o.y = n1 * frcp(d1);
        upk2(nm3, n0, n1); upk2(dn3, d0, d1);
        o.z = n0 * frcp(d0); o.w = n1 * frcp(d1);
        ((float4*)out)[quad1] = o;
    }
}

// ---------------- launch ----------------
extern "C" void kernel_launch(void* const* d_in, const int* in_sizes, int n_in,
                              void* d_out, int out_size) {
    const float* x    = (const float*)d_in[0];
    const float* vals = (const float*)d_in[1];
    const float* pr   = (const float*)d_in[2];
    const float* pim  = (const float*)d_in[3];
    float* out = (float*)d_out;

    k_all<<<GRID, BLOCK>>>(x, vals, pr, pim, out);
}

// round 16
// speedup vs baseline: 1.3852x; 1.1209x over previous
#include <cuda_runtime.h>
#include <math.h>

#define NN       1024
#define NEVALC   131072
#define NPOLES   8
#define NOCT     120          // octets: nodes 32..991
#define NQRT     16           // quartets: nodes 0..31 and 992..1023
#define GRID     128
#define BLOCK    512
#define ESHIFT   1010         // binary recentering ~= 700/ln2 (cancels in num/den)
#define NCU2     ((NOCT * 26 + NQRT * 14) / 2)   // ulonglong2 count = 1672 (26.75 KB)

typedef unsigned long long ull;

// ---------------- compile-time Chebyshev nodes --------------------------------------
constexpr double CPI = 3.141592653589793238462643383279502884;
constexpr double ccos_t(double z) {
    double t = 1.0, s = 1.0, z2 = z * z;
    for (int k = 1; k <= 12; k++) { t *= -z2 / ((2.0 * k - 1.0) * (2.0 * k)); s += t; }
    return s;
}
constexpr double csin_t(double z) {
    double t = z, s = z, z2 = z * z;
    for (int k = 1; k <= 12; k++) { t *= -z2 / ((2.0 * k) * (2.0 * k + 1.0)); s += t; }
    return s;
}
constexpr double cospi_c(double x) {
    double r = x; bool neg = false;
    if (r > 0.5) { r = 1.0 - r; neg = true; }
    double v = (r <= 0.25) ? ccos_t(CPI * r) : csin_t(CPI * (0.5 - r));
    return neg ? -v : v;
}
struct alignas(16) NodeTab { float v[NN]; };
constexpr NodeTab mk_nodes() {
    NodeTab n{};
    for (int i = 0; i < NN; i++) n.v[i] = (float)cospi_c((double)i / 1023.0);
    return n;
}
__device__ constexpr NodeTab c_nodes = mk_nodes();

// ---------------- scratch ----------------
// octet o: 26 dup-packed ull at o*26: [cM, q7..q0, pv7..pv0, pw7..pw0, pad]
// quartet q: 14 ull at 120*26 + q*14: [cM, q3..q0, pv3..pv0, pw3..pw0, pad]
__device__ ulonglong2 g_coef[NCU2];
__device__ unsigned   g_bar;

// ---------------- packed f32x2 helpers ----------------
__device__ __forceinline__ ull pk2(float lo, float hi) {
    ull r; asm("mov.b64 %0,{%1,%2};" : "=l"(r) : "f"(lo), "f"(hi)); return r;
}
__device__ __forceinline__ void upk2(ull v, float& lo, float& hi) {
    asm("mov.b64 {%0,%1},%2;" : "=f"(lo), "=f"(hi) : "l"(v));
}
__device__ __forceinline__ ull f2fma(ull a, ull b, ull c) {
    ull d; asm("fma.rn.f32x2 %0,%1,%2,%3;" : "=l"(d) : "l"(a), "l"(b), "l"(c)); return d;
}
__device__ __forceinline__ ull f2add(ull a, ull b) {
    ull d; asm("add.rn.f32x2 %0,%1,%2;" : "=l"(d) : "l"(a), "l"(b)); return d;
}
__device__ __forceinline__ ull f2rcp(ull q) {
    ull r;
    asm("{.reg .f32 lo, hi;\n\t"
        "mov.b64 {lo, hi}, %1;\n\t"
        "rcp.approx.f32 lo, lo;\n\t"
        "rcp.approx.f32 hi, hi;\n\t"
        "mov.b64 %0, {lo, hi};}"
        : "=l"(r) : "l"(q));
    return r;
}
__device__ __forceinline__ float frcp(float a) {
    float r; asm("rcp.approx.f32 %0,%1;" : "=f"(r) : "f"(a)); return r;
}
__device__ __forceinline__ unsigned ldacq(unsigned* p) {
    unsigned v; asm volatile("ld.acquire.gpu.u32 %0,[%1];" : "=r"(v) : "l"(p)); return v;
}
__device__ __forceinline__ void renorm(float& p, int& e) {
    int b = __float_as_int(p);
    e += (b >> 23) - 127;
    p = __int_as_float((b & 0x007fffff) | 0x3f800000);
}

// ---------------- fused kernel ----------------
__global__ __launch_bounds__(512) void k_all(const float* __restrict__ x,
                                             const float* __restrict__ vals,
                                             const float* __restrict__ pr,
                                             const float* __restrict__ pim,
                                             float* __restrict__ out) {
    __shared__ float snodes[NN];
    __shared__ float sw[12];
    __shared__ ulonglong2 sc[NCU2];            // coeffs; later reused for reduction

    int tid = threadIdx.x;
    int w   = tid >> 5;
    int ln  = tid & 31;
    int b   = blockIdx.x;

    ((float2*)snodes)[tid] = ((const float2*)c_nodes.v)[tid];
    __syncthreads();

    // ---- weights (f32 product + integer exponent tracking; no logf/expf/fp64) ----
    // Block b owns: octet b (nodes 32+8b..) if b<120 -> warps 0..7;
    //               quartet b (nodes 4b or 992+4(b-8)) if b<16 -> warps 8..11.
    {
        int node = -1;
        if (w < 8) { if (b < NOCT) node = 32 + 8 * b + w; }
        else if (w < 12) { if (b < NQRT) node = ((b < 8) ? 4 * b : 992 + 4 * (b - 8)) + (w - 8); }
        if (node >= 0) {
            float nj = snodes[node];
            float p = 1.0f; int e = 0;
            #pragma unroll 4
            for (int i = ln; i < NN; i += 32) {
                float d = (i != node) ? fabsf(nj - snodes[i]) : 1.0f;
                p *= d;
                renorm(p, e);
            }
            #pragma unroll
            for (int off = 16; off; off >>= 1) {
                p *= __shfl_xor_sync(0xffffffffu, p, off);
                e += __shfl_xor_sync(0xffffffffu, e, off);
                renorm(p, e);
            }
            if (ln == 0) {
                float pp = 1.0f; int ep = 0;
                #pragma unroll
                for (int q = 0; q < NPOLES; q++) {
                    float dr = nj - pr[q];
                    float inner = dr * dr + pim[q] * pim[q];
                    pp *= inner;
                    renorm(pp, ep);
                }
                float m  = pp * frcp(p);
                float wv = ldexpf(m, ep - e - ESHIFT);
                sw[w] = (node & 1) ? -wv : wv;   // sign = (-1)^j
            }
        }
    }
    __syncthreads();

    // ---- octet coefficients (warp 12, f32 build — absolute errors ~eps32*|e_k|,
    //      same scale as the f32 Horner eval error; cuts the serial chain 47->4 cyc) ----
    if (w == 12 && b < NOCT) {
        bool act = ln < 8;
        int nodei = 32 + 8 * b + (ln & 7);
        float nd = act ? snodes[nodei] : 0.0f;
        float s = nd;
        s += __shfl_xor_sync(0xffffffffu, s, 1);
        s += __shfl_xor_sync(0xffffffffu, s, 2);
        s += __shfl_xor_sync(0xffffffffu, s, 4);
        float cf = 0.125f * s;
        float di = nd - cf;
        float dd[8];
        #pragma unroll
        for (int k = 0; k < 8; k++) dd[k] = __shfl_sync(0xffffffffu, di, k);
        float C[9];
        C[0] = 1.0f;
        #pragma unroll
        for (int k = 1; k < 9; k++) C[k] = 0.0f;
        #pragma unroll
        for (int r = 0; r < 8; r++) {
            #pragma unroll
            for (int k = 8; k >= 1; k--) C[k] = C[k - 1] - dd[r] * C[k];
            C[0] = -dd[r] * C[0];
        }
        float B[8];
        B[7] = 1.0f;
        #pragma unroll
        for (int k = 6; k >= 0; k--) B[k] = C[k + 1] + di * B[k + 1];
        float u  = act ? sw[ln & 7] : 0.0f;
        float uv = u * (act ? vals[nodei] : 0.0f);
        float pv[8], pw[8];
        #pragma unroll
        for (int k = 0; k < 8; k++) {
            float a = uv * B[k], c2 = u * B[k];
            #pragma unroll
            for (int off = 4; off; off >>= 1) {
                a  += __shfl_xor_sync(0xffffffffu, a, off);
                c2 += __shfl_xor_sync(0xffffffffu, c2, off);
            }
            pv[k] = a; pw[k] = c2;
        }
        if (ln == 0) {
            ull* cc = (ull*)g_coef + (size_t)b * 26;
            float f;
            f = -cf;           cc[0]  = pk2(f, f);
            #pragma unroll
            for (int k = 0; k < 8; k++) { f = C[7 - k];  cc[1 + k]  = pk2(f, f); }
            #pragma unroll
            for (int k = 0; k < 8; k++) { f = pv[7 - k]; cc[9 + k]  = pk2(f, f); }
            #pragma unroll
            for (int k = 0; k < 8; k++) { f = pw[7 - k]; cc[17 + k] = pk2(f, f); }
            cc[25] = 0ull;
            __threadfence();
        }
    }

    // ---- quartet coefficients (warp 13, f32 build) ----
    if (w == 13 && b < NQRT) {
        bool act = ln < 4;
        int nb = (b < 8) ? 4 * b : 992 + 4 * (b - 8);
        int nodei = nb + (ln & 3);
        float nd = act ? snodes[nodei] : 0.0f;
        float s = nd;
        s += __shfl_xor_sync(0xffffffffu, s, 1);
        s += __shfl_xor_sync(0xffffffffu, s, 2);
        float cf = 0.25f * s;
        float di = nd - cf;
        float dd[4];
        #pragma unroll
        for (int k = 0; k < 4; k++) dd[k] = __shfl_sync(0xffffffffu, di, k);
        float C[5];
        C[0] = 1.0f;
        #pragma unroll
        for (int k = 1; k < 5; k++) C[k] = 0.0f;
        #pragma unroll
        for (int r = 0; r < 4; r++) {
            #pragma unroll
            for (int k = 4; k >= 1; k--) C[k] = C[k - 1] - dd[r] * C[k];
            C[0] = -dd[r] * C[0];
        }
        float B[4];
        B[3] = 1.0f;
        #pragma unroll
        for (int k = 2; k >= 0; k--) B[k] = C[k + 1] + di * B[k + 1];
        float u  = act ? sw[8 + (ln & 3)] : 0.0f;
        float uv = u * (act ? vals[nodei] : 0.0f);
        float pv[4], pw[4];
        #pragma unroll
        for (int k = 0; k < 4; k++) {
            float a = uv * B[k], c2 = u * B[k];
            #pragma unroll
            for (int off = 2; off; off >>= 1) {
                a  += __shfl_xor_sync(0xffffffffu, a, off);
                c2 += __shfl_xor_sync(0xffffffffu, c2, off);
            }
            pv[k] = a; pw[k] = c2;
        }
        if (ln == 0) {
            ull* cc = (ull*)g_coef + (size_t)NOCT * 26 + (size_t)b * 14;
            float f;
            f = -cf;           cc[0]  = pk2(f, f);
            #pragma unroll
            for (int k = 0; k < 4; k++) { f = C[3 - k];  cc[1 + k] = pk2(f, f); }
            #pragma unroll
            for (int k = 0; k < 4; k++) { f = pv[3 - k]; cc[5 + k] = pk2(f, f); }
            #pragma unroll
            for (int k = 0; k < 4; k++) { f = pw[3 - k]; cc[9 + k] = pk2(f, f); }
            cc[13] = 0ull;
            __threadfence();
        }
    }

    // ---- x loads (hidden behind the barrier) ----
    int part  = tid >> 7;                      // group partition 0..3
    int lane  = tid & 127;                     // point-lane
    int quad0 = b * 256 + lane;
    int quad1 = quad0 + 128;
    float4 va = ((const float4*)x)[quad0];
    float4 vb = ((const float4*)x)[quad1];
    ull xp0 = pk2(va.x, va.y), xp1 = pk2(va.z, va.w);
    ull xp2 = pk2(vb.x, vb.y), xp3 = pk2(vb.z, vb.w);

    // ---- grid barrier (monotonic tickets; 1 block/SM) ----
    __syncthreads();
    if (tid == 0) {
        unsigned ticket = atomicAdd(&g_bar, 1u);
        unsigned target = (ticket / GRID + 1u) * GRID;
        while (ldacq(&g_bar) < target) { }
    }
    __syncthreads();

    // ---- load all coefficients into smem ----
    {
        const uint4* src = (const uint4*)g_coef;
        uint4* dst = (uint4*)sc;
        #pragma unroll
        for (int i = tid; i < NCU2; i += BLOCK) dst[i] = src[i];
    }
    __syncthreads();

    // ---- eval: 8 pts/thread (4 packed pairs), split-4, unmerged rcp.
    //      Q-coefficient half (cM,q7..q0) is double-buffered one iteration ahead so
    //      the t/q Horner chains never wait on loop-top LDS latency.
    ull nm0 = 0, dn0 = 0, nm1 = 0, dn1 = 0, nm2 = 0, dn2 = 0, nm3 = 0, dn3 = 0;

    const ulonglong2* cp = sc + (size_t)(30 * part) * 13;
    ulonglong2 p0 = cp[0], p1 = cp[1], p2 = cp[2], p3 = cp[3], p4 = cp[4];

    #pragma unroll 2
    for (int i = 0; i < 30; i++) {
        ulonglong2 a0 = p0, a1 = p1, a2 = p2, a3 = p3, a4 = p4;
        ulonglong2 a5 = cp[5], a6 = cp[6], a7 = cp[7],  a8 = cp[8],  a9 = cp[9],
                   a10 = cp[10], a11 = cp[11], a12 = cp[12];
        cp += 13;
        p0 = cp[0]; p1 = cp[1]; p2 = cp[2]; p3 = cp[3]; p4 = cp[4];   // prefetch
        // (over-read on last iter stays inside sc: max offset 1573 < 1672)

        #define GRPOCT(XP, NM, DN)                                            \
        {                                                                     \
            ull t = f2add(XP, a0.x);           /* t = x - c */                \
            ull q = f2add(t, a0.y);            /* monic octic Horner */       \
            q = f2fma(q, t, a1.x);   q = f2fma(q, t, a1.y);                   \
            q = f2fma(q, t, a2.x);   q = f2fma(q, t, a2.y);                   \
            q = f2fma(q, t, a3.x);   q = f2fma(q, t, a3.y);                   \
            q = f2fma(q, t, a4.x);                                            \
            ull v = f2fma(a4.y, t, a5.x);      /* septic num */               \
            v = f2fma(v, t, a5.y);   v = f2fma(v, t, a6.x);                   \
            v = f2fma(v, t, a6.y);   v = f2fma(v, t, a7.x);                   \
            v = f2fma(v, t, a7.y);   v = f2fma(v, t, a8.x);                   \
            ull wv = f2fma(a8.y, t, a9.x);     /* septic den */               \
            wv = f2fma(wv, t, a9.y);  wv = f2fma(wv, t, a10.x);               \
            wv = f2fma(wv, t, a10.y); wv = f2fma(wv, t, a11.x);               \
            wv = f2fma(wv, t, a11.y); wv = f2fma(wv, t, a12.x);               \
            ull r = f2rcp(q);                  /* 1 packed rcp / 8 nodes */   \
            NM = f2fma(v, r, NM);                                             \
            DN = f2fma(wv, r, DN);                                            \
        }
        GRPOCT(xp0, nm0, dn0)
        GRPOCT(xp1, nm1, dn1)
        GRPOCT(xp2, nm2, dn2)
        GRPOCT(xp3, nm3, dn3)
        #undef GRPOCT
    }

    // quartets {2p, 2p+1, 2p+8, 2p+9}
    {
        const ulonglong2* qb = sc + (size_t)NOCT * 13;
        #pragma unroll
        for (int k = 0; k < 4; k++) {
            int qi = (k < 2) ? (2 * part + k) : (2 * part + 8 + (k - 2));
            const ulonglong2* A = qb + (size_t)qi * 7;
            ulonglong2 a0 = A[0], a1 = A[1], a2 = A[2], a3 = A[3],
                       a4 = A[4], a5 = A[5], a6 = A[6];

            #define GRPQRT(XP, NM, DN)                                        \
            {                                                                 \
                ull t = f2add(XP, a0.x);                                      \
                ull q = f2add(t, a0.y);        /* monic quartic Horner */     \
                q = f2fma(q, t, a1.x);  q = f2fma(q, t, a1.y);                \
                q = f2fma(q, t, a2.x);                                        \
                ull v = f2fma(a2.y, t, a3.x);  /* cubic num */                \
                v = f2fma(v, t, a3.y);  v = f2fma(v, t, a4.x);                \
                ull wv = f2fma(a4.y, t, a5.x); /* cubic den */                \
                wv = f2fma(wv, t, a5.y); wv = f2fma(wv, t, a6.x);             \
                ull r = f2rcp(q);                                             \
                NM = f2fma(v, r, NM);                                         \
                DN = f2fma(wv, r, DN);                                        \
            }
            GRPQRT(xp0, nm0, dn0)
            GRPQRT(xp1, nm1, dn1)
            GRPQRT(xp2, nm2, dn2)
            GRPQRT(xp3, nm3, dn3)
            #undef GRPQRT
        }
    }

    // ---- cross-partition reduction (reuse sc) + divide + store ----
    __syncthreads();
    ull (*sred)[128][8] = (ull(*)[128][8])sc;   // 3 x 128 x 8 x 8B = 24 KB <= 26.75 KB
    if (part) {
        ull* dst = sred[part - 1][lane];
        dst[0] = nm0; dst[1] = dn0; dst[2] = nm1; dst[3] = dn1;
        dst[4] = nm2; dst[5] = dn2; dst[6] = nm3; dst[7] = dn3;
    }
    __syncthreads();
    if (part == 0) {
        #pragma unroll
        for (int p = 0; p < 3; p++) {
            const ull* s = sred[p][lane];
            nm0 = f2add(nm0, s[0]); dn0 = f2add(dn0, s[1]);
            nm1 = f2add(nm1, s[2]); dn1 = f2add(dn1, s[3]);
            nm2 = f2add(nm2, s[4]); dn2 = f2add(dn2, s[5]);
            nm3 = f2add(nm3, s[6]); dn3 = f2add(dn3, s[7]);
        }
        float n0, n1, d0, d1;
        float4 o;
        upk2(nm0, n0, n1); upk2(dn0, d0, d1);
        o.x = n0 * frcp(d0); o.y = n1 * frcp(d1);
        upk2(nm1, n0, n1); upk2(dn1, d0, d1);
        o.z = n0 * frcp(d0); o.w = n1 * frcp(d1);
        ((float4*)out)[quad0] = o;
        upk2(nm2, n0, n1); upk2(dn2, d0, d1);
        o.x = n0 * frcp(d0); o.y = n1 * frcp(d1);
        upk2(nm3, n0, n1); upk2(dn3, d0, d1);
        o.z = n0 * frcp(d0); o.w = n1 * frcp(d1);
        ((float4*)out)[quad1] = o;
    }
}

// ---------------- launch ----------------
extern "C" void kernel_launch(void* const* d_in, const int* in_sizes, int n_in,
                              void* d_out, int out_size) {
    const float* x    = (const float*)d_in[0];
    const float* vals = (const float*)d_in[1];
    const float* pr   = (const float*)d_in[2];
    const float* pim  = (const float*)d_in[3];
    float* out = (float*)d_out;

    k_all<<<GRID, BLOCK>>>(x, vals, pr, pim, out);
}